// round 15
// baseline (speedup 1.0000x reference)
#include <cuda_runtime.h>
#include <cuda_fp16.h>

#define Nn   4096
#define INF_ 256
#define OUTF 64
#define KH   4
#define SEG  128          // K2 i-segments (2048 blocks -> good wave packing)
#define JC   8            // j-chunks
#define JW   512          // j per chunk
#define IC   32           // i-chunks (grid 1024 -> 3.46 waves, small tail)
#define IR   128          // rows per chunk
#define L2E  1.44269504088896f

// ---- scratch (no allocations allowed) ----
__device__ __half2 g_Whh[Nn * (OUTF / 2)];   // Wh fp16, row j = 32 half2
__device__ float g_Wh1[Nn];                  // (Wh@a[:64]) * log2e
__device__ float g_Wh2[Nn];                  // (Wh@a[64:]) * log2e
__device__ float g_ps[SEG * KH * Nn];        // partial col sums (8MB)
__device__ float g_li[KH * Nn];              // -log2(sum) per column
__device__ unsigned char g_flag[KH * Nn];    // all-masked column flag
__device__ int g_patho;
__device__ float g_part[JC * KH * Nn * OUTF];// spmv partials per j-chunk

__device__ __forceinline__ float ex2(float x) {
    float r; asm("ex2.approx.f32 %0, %1;" : "=f"(r) : "f"(x)); return r;
}
__device__ __forceinline__ void pf_l2(const void* p) {
    asm volatile("prefetch.global.L2 [%0];" :: "l"(p));
}

// exp2 on the FMA/ALU pipes (no MUFU). |e| < 50. rel err ~1e-7.
__device__ __forceinline__ float exp2_poly(float e) {
    float t = e + 12582912.0f;             // 1.5 * 2^23, RN -> k in low bits
    int   ki = __float_as_int(t);
    float k  = t - 12582912.0f;
    float f  = e - k;                      // [-0.5, 0.5] exact
    float p  = 1.5361332e-4f;
    p = fmaf(p, f, 1.3333558e-3f);
    p = fmaf(p, f, 9.6181291e-3f);
    p = fmaf(p, f, 5.5504109e-2f);
    p = fmaf(p, f, 2.4022651e-1f);
    p = fmaf(p, f, 6.9314718e-1f);
    p = fmaf(p, f, 1.0f);
    return __int_as_float(__float_as_int(p) + (ki << 23));
}

// ============================================================
// K1: Wh = h @ W (stored fp16 for the spmv);
// Wh1/Wh2 = (Wh@a halves) * log2e (exact fold).
// ============================================================
__global__ void __launch_bounds__(256) k1_wh(const float* __restrict__ h,
                                             const float* __restrict__ W,
                                             const float* __restrict__ a) {
    __shared__ float sh[4][INF_];
    __shared__ float s1[4], s2[4];
    int t = threadIdx.x;
    int row0 = blockIdx.x * 4;

    for (int q = t; q < 4 * INF_; q += 256)
        sh[q >> 8][q & 255] = h[(size_t)row0 * INF_ + q];
    if (t < 4) { s1[t] = 0.f; s2[t] = 0.f; }
    if (blockIdx.x == 0 && t == 0) g_patho = 0;
    __syncthreads();

    int r = t >> 6, f = t & 63;
    float acc = 0.f;
#pragma unroll 8
    for (int c = 0; c < INF_; ++c)
        acc += sh[r][c] * W[c * OUTF + f];

    float hi = __shfl_down_sync(0xffffffffu, acc, 1);
    if ((f & 1) == 0)
        g_Whh[(size_t)(row0 + r) * (OUTF / 2) + (f >> 1)] = __floats2half2_rn(acc, hi);

    float p1 = acc * a[f];
    float p2 = acc * a[OUTF + f];
#pragma unroll
    for (int o = 16; o; o >>= 1) {
        p1 += __shfl_down_sync(0xffffffffu, p1, o);
        p2 += __shfl_down_sync(0xffffffffu, p2, o);
    }
    if ((t & 31) == 0) { atomicAdd(&s1[r], p1); atomicAdd(&s2[r], p2); }
    __syncthreads();
    if (t < 4) { g_Wh1[row0 + t] = s1[t] * L2E; g_Wh2[row0 + t] = s2[t] * L2E; }
}

// ============================================================
// K2 (monolithic, all k): column sums of 2^e over axis i.
// grid = k(4) x jt(4) x seg(128) = 2048 blocks of 256 (32 rows each).
// ============================================================
__global__ void __launch_bounds__(256) k2_stats(const float* __restrict__ edge) {
    int b = blockIdx.x;
    int seg = b & (SEG - 1); b /= SEG;
    int jt = b & 3;
    int k  = b >> 2;
    int q = jt * 256 + threadIdx.x;
    const float4* base = (const float4*)(edge + (size_t)k * Nn * Nn) + q;
    float4 w2 = ((const float4*)g_Wh2)[q];

    float4 s = make_float4(0.f, 0.f, 0.f, 0.f);
    int i0 = seg * (Nn / SEG);
    int iend = i0 + Nn / SEG;
#pragma unroll 4
    for (int i = i0; i < iend; ++i) {
        float4 x = __ldcs(base + (size_t)i * (Nn / 4));
        if (i + 4 < iend) pf_l2(base + (size_t)(i + 4) * (Nn / 4));
        float w1 = g_Wh1[i];
        float tt, lk, v;
        tt = w1 + w2.x; lk = fmaxf(tt, 0.2f * tt);
        v = exp2_poly(lk * x.x); s.x += (x.x > 0.f) ? v : 0.f;
        tt = w1 + w2.y; lk = fmaxf(tt, 0.2f * tt);
        v = exp2_poly(lk * x.y); s.y += (x.y > 0.f) ? v : 0.f;
        tt = w1 + w2.z; lk = fmaxf(tt, 0.2f * tt);
        v = exp2_poly(lk * x.z); s.z += (x.z > 0.f) ? v : 0.f;
        tt = w1 + w2.w; lk = fmaxf(tt, 0.2f * tt);
        v = exp2_poly(lk * x.w); s.w += (x.w > 0.f) ? v : 0.f;
    }
    ((float4*)g_ps)[(size_t)seg * (KH * Nn / 4) + k * (Nn / 4) + q] = s;
}

// ============================================================
// K2b: merge segments -> li = -log2(sum). Empty column -> 1/N.
// ============================================================
__global__ void __launch_bounds__(256) k2_merge() {
    int col = blockIdx.x * 256 + threadIdx.x;
    float s = 0.f;
#pragma unroll 8
    for (int g = 0; g < SEG; ++g)
        s += g_ps[(size_t)g * (KH * Nn) + col];
    if (s > 0.f) {
        g_li[col] = -log2f(s);
        g_flag[col] = 0;
    } else {
        g_li[col] = -12.0f;                // 2^-12 = 1/N
        g_flag[col] = 1;
        atomicAdd(&g_patho, 1);
    }
}

// ============================================================
// K3 (monolithic): block = (k, jc, ic), 1024 threads, Wh chunk
// in 64KB smem fp16; att = EX2(lk*x + li); bit-walk spmv vs
// SMEM; unconditional next-row L2 prefetch. IC=32 (grid 1024,
// 3.46 waves -> small tail; R12 showed this block shape at 88%
// occ; R13 showed the tail of grid 512 costs ~7%).
// ============================================================
__global__ void __launch_bounds__(1024, 2) k3_chunk(const float* __restrict__ edge,
                                                    float* __restrict__ att_out,
                                                    int write_att) {
    extern __shared__ __half2 swh[];       // [JW][32] = 64KB

    int b = blockIdx.x;
    int ic = b & 31; b >>= 5;
    int jc = b & 7;  b >>= 3;
    int k  = b;
    int j0 = jc * JW;
    int i0 = ic * IR;
    int t = threadIdx.x, lane = t & 31, w = t >> 5;

    {
        const __half2* src = g_Whh + (size_t)j0 * (OUTF / 2);
#pragma unroll 4
        for (int q = t; q < JW * (OUTF / 2); q += 1024)
            swh[q] = src[q];
    }
    __syncthreads();

    const float4* w2v = (const float4*)g_Wh2 + (j0 >> 2);
    const float4* liv = (const float4*)(g_li + k * Nn) + (j0 >> 2);
    const unsigned char* flag = g_flag + k * Nn + j0;
    int patho = g_patho;

#pragma unroll 1
    for (int r = 0; r < IR / 32; ++r) {     // 4 rows per warp
        int i = i0 + w * (IR / 32) + r;
        float w1 = g_Wh1[i];
        const float4* erow = (const float4*)(edge + ((size_t)k * Nn + i) * Nn + j0);
        float4* arow = (float4*)(att_out + ((size_t)k * Nn + i) * Nn + j0);
        float2 acc = make_float2(0.f, 0.f);
        bool pf = (i + 1) < Nn;             // next row (maybe next warp's)

#pragma unroll
        for (int g = 0; g < 4; ++g) {
            int q = g * 32 + lane;          // float4 index within chunk
            float4 x  = __ldcs(erow + q);
            if (pf) pf_l2(erow + q + (Nn / 4));
            float4 w2 = w2v[q];
            float4 li = liv[q];
            int jlu = g * 128;              // warp-uniform local j base
            float4 att = make_float4(0.f, 0.f, 0.f, 0.f);

#define COMP(CX, CW2, CLI, CA, CC)                                          \
            {                                                                \
                unsigned m = __ballot_sync(0xffffffffu, (CX) > 0.f);         \
                if (m) {                                                     \
                    float tt = w1 + (CW2);                                   \
                    float lk = fmaxf(tt, 0.2f * tt);                         \
                    float v  = ex2(fmaf(lk, (CX), (CLI)));                   \
                    if ((CX) > 0.f) (CA) = v;                                \
                    const __half2* p = swh + (jlu + (CC)) * 32 + lane;       \
                    while (m) {                                              \
                        int bb = __ffs(m) - 1; m &= m - 1;                   \
                        float aa = __shfl_sync(0xffffffffu, (CA), bb);       \
                        float2 wv = __half22float2(p[bb * 128]);             \
                        acc.x = fmaf(aa, wv.x, acc.x);                       \
                        acc.y = fmaf(aa, wv.y, acc.y);                       \
                    }                                                        \
                }                                                            \
            }
            COMP(x.x, w2.x, li.x, att.x, 0)
            COMP(x.y, w2.y, li.y, att.y, 1)
            COMP(x.z, w2.z, li.z, att.z, 2)
            COMP(x.w, w2.w, li.w, att.w, 3)
#undef COMP

            if (patho) {                    // never taken in practice
                int jl = q * 4;
                if (x.x <= 0.f && flag[jl + 0]) att.x = ex2(li.x);
                if (x.y <= 0.f && flag[jl + 1]) att.y = ex2(li.y);
                if (x.z <= 0.f && flag[jl + 2]) att.z = ex2(li.z);
                if (x.w <= 0.f && flag[jl + 3]) att.w = ex2(li.w);
            }
            if (write_att) __stcs(arow + q, att);
        }

        // one writer per (jc,k,i,f) slot — deterministic, no atomics
        float2* pp = (float2*)(g_part + (((size_t)jc * KH + k) * Nn + i) * OUTF);
        __stcs(pp + lane, acc);
    }
}

// ============================================================
// K4: reduce partials over j-chunks, apply elu, write out.
// ============================================================
__global__ void __launch_bounds__(256) k4_reduce(float* __restrict__ out) {
    int idx = blockIdx.x * 256 + threadIdx.x;   // over Nn*KH*OUTF
    int i = idx >> 8, rem = idx & 255;
    int k = rem >> 6, f = rem & 63;
    float v = 0.f;
#pragma unroll
    for (int jc = 0; jc < JC; ++jc)
        v += __ldcs(&g_part[(((size_t)jc * KH + k) * Nn + i) * OUTF + f]);
    v = v > 0.f ? v : expm1f(v);
    out[idx] = v;
}

// ============================================================
extern "C" void kernel_launch(void* const* d_in, const int* in_sizes, int n_in,
                              void* d_out, int out_size) {
    const float *h = nullptr, *edge = nullptr, *W = nullptr, *a = nullptr;
    for (int q = 0; q < n_in; ++q) {
        switch (in_sizes[q]) {
            case Nn * INF_:    h = (const float*)d_in[q]; break;
            case INF_ * OUTF:  W = (const float*)d_in[q]; break;
            case 2 * OUTF:     a = (const float*)d_in[q]; break;
            default:
                if (in_sizes[q] == KH * Nn * Nn) edge = (const float*)d_in[q];
                break;
        }
    }
    if (!h || !edge || !W || !a) {
        if (n_in >= 4) {
            h    = (const float*)d_in[0];
            edge = (const float*)d_in[1];
            W    = (const float*)d_in[2];
            a    = (const float*)d_in[3];
        }
    }

    const long n_elu = (long)Nn * KH * OUTF;
    const long n_att = (long)KH * Nn * Nn;
    float* out = (float*)d_out;
    float* attp = out;
    int write_att = 0;
    if ((long)out_size >= n_elu + n_att) {
        attp = out + n_elu;
        write_att = 1;
    }

    const int smem = JW * (OUTF / 2) * (int)sizeof(__half2);   // 64KB
    cudaFuncSetAttribute(k3_chunk, cudaFuncAttributeMaxDynamicSharedMemorySize, smem);

    k1_wh   <<<Nn / 4,             256>>>(h, W, a);
    k2_stats<<<KH * 4 * SEG,       256>>>(edge);
    k2_merge<<<KH * Nn / 256,      256>>>();
    k3_chunk<<<KH * JC * IC,       1024, smem>>>(edge, attp, write_att);
    k4_reduce<<<Nn * KH * OUTF / 256, 256>>>(out);
}

// round 16
// speedup vs baseline: 1.0172x; 1.0172x over previous
#include <cuda_runtime.h>
#include <cuda_fp16.h>

#define Nn   4096
#define INF_ 256
#define OUTF 64
#define KH   4
#define SEG  64           // K2 i-segments (R14-measured best)
#define JC   8            // j-chunks
#define JW   512          // j per chunk
#define IC   32           // i-chunks (R15-measured best for K3)
#define IR   128          // rows per chunk
#define L2E  1.44269504088896f

// ---- scratch (no allocations allowed) ----
__device__ __half2 g_Whh[Nn * (OUTF / 2)];   // Wh fp16, row j = 32 half2
__device__ float g_Wh1[Nn];                  // (Wh@a[:64]) * log2e
__device__ float g_Wh2[Nn];                  // (Wh@a[64:]) * log2e
__device__ float g_ps[SEG * KH * Nn];        // partial col sums
__device__ float g_li[KH * Nn];              // -log2(sum) per column
__device__ unsigned char g_flag[KH * Nn];    // all-masked column flag
__device__ int g_patho;
__device__ float g_part[JC * KH * Nn * OUTF];// spmv partials per j-chunk

__device__ __forceinline__ float ex2(float x) {
    float r; asm("ex2.approx.f32 %0, %1;" : "=f"(r) : "f"(x)); return r;
}
__device__ __forceinline__ void pf_l2(const void* p) {
    asm volatile("prefetch.global.L2 [%0];" :: "l"(p));
}

// exp2 on the FMA/ALU pipes (no MUFU). |e| < 50. rel err ~1e-7.
__device__ __forceinline__ float exp2_poly(float e) {
    float t = e + 12582912.0f;             // 1.5 * 2^23, RN -> k in low bits
    int   ki = __float_as_int(t);
    float k  = t - 12582912.0f;
    float f  = e - k;                      // [-0.5, 0.5] exact
    float p  = 1.5361332e-4f;
    p = fmaf(p, f, 1.3333558e-3f);
    p = fmaf(p, f, 9.6181291e-3f);
    p = fmaf(p, f, 5.5504109e-2f);
    p = fmaf(p, f, 2.4022651e-1f);
    p = fmaf(p, f, 6.9314718e-1f);
    p = fmaf(p, f, 1.0f);
    return __int_as_float(__float_as_int(p) + (ki << 23));
}

// ============================================================
// K1: Wh = h @ W (stored fp16 for the spmv);
// Wh1/Wh2 = (Wh@a halves) * log2e (exact fold).
// ============================================================
__global__ void __launch_bounds__(256) k1_wh(const float* __restrict__ h,
                                             const float* __restrict__ W,
                                             const float* __restrict__ a) {
    __shared__ float sh[4][INF_];
    __shared__ float s1[4], s2[4];
    int t = threadIdx.x;
    int row0 = blockIdx.x * 4;

    for (int q = t; q < 4 * INF_; q += 256)
        sh[q >> 8][q & 255] = h[(size_t)row0 * INF_ + q];
    if (t < 4) { s1[t] = 0.f; s2[t] = 0.f; }
    if (blockIdx.x == 0 && t == 0) g_patho = 0;
    __syncthreads();

    int r = t >> 6, f = t & 63;
    float acc = 0.f;
#pragma unroll 8
    for (int c = 0; c < INF_; ++c)
        acc += sh[r][c] * W[c * OUTF + f];

    float hi = __shfl_down_sync(0xffffffffu, acc, 1);
    if ((f & 1) == 0)
        g_Whh[(size_t)(row0 + r) * (OUTF / 2) + (f >> 1)] = __floats2half2_rn(acc, hi);

    float p1 = acc * a[f];
    float p2 = acc * a[OUTF + f];
#pragma unroll
    for (int o = 16; o; o >>= 1) {
        p1 += __shfl_down_sync(0xffffffffu, p1, o);
        p2 += __shfl_down_sync(0xffffffffu, p2, o);
    }
    if ((t & 31) == 0) { atomicAdd(&s1[r], p1); atomicAdd(&s2[r], p2); }
    __syncthreads();
    if (t < 4) { g_Wh1[row0 + t] = s1[t] * L2E; g_Wh2[row0 + t] = s2[t] * L2E; }
}

// ============================================================
// K2 (monolithic, all k): column sums of 2^e over axis i.
// grid = k(4) x jt(4) x seg(64) = 1024 blocks of 256.
// ============================================================
__global__ void __launch_bounds__(256) k2_stats(const float* __restrict__ edge) {
    int b = blockIdx.x;
    int seg = b & (SEG - 1); b /= SEG;
    int jt = b & 3;
    int k  = b >> 2;
    int q = jt * 256 + threadIdx.x;
    const float4* base = (const float4*)(edge + (size_t)k * Nn * Nn) + q;
    float4 w2 = ((const float4*)g_Wh2)[q];

    float4 s = make_float4(0.f, 0.f, 0.f, 0.f);
    int i0 = seg * (Nn / SEG);
    int iend = i0 + Nn / SEG;
#pragma unroll 4
    for (int i = i0; i < iend; ++i) {
        float4 x = __ldcs(base + (size_t)i * (Nn / 4));
        if (i + 4 < iend) pf_l2(base + (size_t)(i + 4) * (Nn / 4));
        float w1 = g_Wh1[i];
        float tt, lk, v;
        tt = w1 + w2.x; lk = fmaxf(tt, 0.2f * tt);
        v = exp2_poly(lk * x.x); s.x += (x.x > 0.f) ? v : 0.f;
        tt = w1 + w2.y; lk = fmaxf(tt, 0.2f * tt);
        v = exp2_poly(lk * x.y); s.y += (x.y > 0.f) ? v : 0.f;
        tt = w1 + w2.z; lk = fmaxf(tt, 0.2f * tt);
        v = exp2_poly(lk * x.z); s.z += (x.z > 0.f) ? v : 0.f;
        tt = w1 + w2.w; lk = fmaxf(tt, 0.2f * tt);
        v = exp2_poly(lk * x.w); s.w += (x.w > 0.f) ? v : 0.f;
    }
    ((float4*)g_ps)[(size_t)seg * (KH * Nn / 4) + k * (Nn / 4) + q] = s;
}

// ============================================================
// K2b: merge segments -> li = -log2(sum). Empty column -> 1/N.
// ============================================================
__global__ void __launch_bounds__(256) k2_merge() {
    int col = blockIdx.x * 256 + threadIdx.x;
    float s = 0.f;
#pragma unroll
    for (int g = 0; g < SEG; ++g)
        s += g_ps[(size_t)g * (KH * Nn) + col];
    if (s > 0.f) {
        g_li[col] = -log2f(s);
        g_flag[col] = 0;
    } else {
        g_li[col] = -12.0f;                // 2^-12 = 1/N
        g_flag[col] = 1;
        atomicAdd(&g_patho, 1);
    }
}

// ============================================================
// K3 (monolithic): block = (k, jc, ic), 1024 threads, Wh chunk
// in 64KB smem fp16; att = EX2(lk*x + li); bit-walk spmv vs
// SMEM; unconditional next-row L2 prefetch. IC=32: grid 1024,
// 3.46 waves -> small quantization tail (measured 111.7us).
// ============================================================
__global__ void __launch_bounds__(1024, 2) k3_chunk(const float* __restrict__ edge,
                                                    float* __restrict__ att_out,
                                                    int write_att) {
    extern __shared__ __half2 swh[];       // [JW][32] = 64KB

    int b = blockIdx.x;
    int ic = b & 31; b >>= 5;
    int jc = b & 7;  b >>= 3;
    int k  = b;
    int j0 = jc * JW;
    int i0 = ic * IR;
    int t = threadIdx.x, lane = t & 31, w = t >> 5;

    {
        const __half2* src = g_Whh + (size_t)j0 * (OUTF / 2);
#pragma unroll 4
        for (int q = t; q < JW * (OUTF / 2); q += 1024)
            swh[q] = src[q];
    }
    __syncthreads();

    const float4* w2v = (const float4*)g_Wh2 + (j0 >> 2);
    const float4* liv = (const float4*)(g_li + k * Nn) + (j0 >> 2);
    const unsigned char* flag = g_flag + k * Nn + j0;
    int patho = g_patho;

#pragma unroll 1
    for (int r = 0; r < IR / 32; ++r) {     // 4 rows per warp
        int i = i0 + w * (IR / 32) + r;
        float w1 = g_Wh1[i];
        const float4* erow = (const float4*)(edge + ((size_t)k * Nn + i) * Nn + j0);
        float4* arow = (float4*)(att_out + ((size_t)k * Nn + i) * Nn + j0);
        float2 acc = make_float2(0.f, 0.f);
        bool pf = (i + 1) < Nn;             // next row (maybe next warp's)

#pragma unroll
        for (int g = 0; g < 4; ++g) {
            int q = g * 32 + lane;          // float4 index within chunk
            float4 x  = __ldcs(erow + q);
            if (pf) pf_l2(erow + q + (Nn / 4));
            float4 w2 = w2v[q];
            float4 li = liv[q];
            int jlu = g * 128;              // warp-uniform local j base
            float4 att = make_float4(0.f, 0.f, 0.f, 0.f);

#define COMP(CX, CW2, CLI, CA, CC)                                          \
            {                                                                \
                unsigned m = __ballot_sync(0xffffffffu, (CX) > 0.f);         \
                if (m) {                                                     \
                    float tt = w1 + (CW2);                                   \
                    float lk = fmaxf(tt, 0.2f * tt);                         \
                    float v  = ex2(fmaf(lk, (CX), (CLI)));                   \
                    if ((CX) > 0.f) (CA) = v;                                \
                    const __half2* p = swh + (jlu + (CC)) * 32 + lane;       \
                    while (m) {                                              \
                        int bb = __ffs(m) - 1; m &= m - 1;                   \
                        float aa = __shfl_sync(0xffffffffu, (CA), bb);       \
                        float2 wv = __half22float2(p[bb * 128]);             \
                        acc.x = fmaf(aa, wv.x, acc.x);                       \
                        acc.y = fmaf(aa, wv.y, acc.y);                       \
                    }                                                        \
                }                                                            \
            }
            COMP(x.x, w2.x, li.x, att.x, 0)
            COMP(x.y, w2.y, li.y, att.y, 1)
            COMP(x.z, w2.z, li.z, att.z, 2)
            COMP(x.w, w2.w, li.w, att.w, 3)
#undef COMP

            if (patho) {                    // never taken in practice
                int jl = q * 4;
                if (x.x <= 0.f && flag[jl + 0]) att.x = ex2(li.x);
                if (x.y <= 0.f && flag[jl + 1]) att.y = ex2(li.y);
                if (x.z <= 0.f && flag[jl + 2]) att.z = ex2(li.z);
                if (x.w <= 0.f && flag[jl + 3]) att.w = ex2(li.w);
            }
            if (write_att) __stcs(arow + q, att);
        }

        // one writer per (jc,k,i,f) slot — deterministic, no atomics
        float2* pp = (float2*)(g_part + (((size_t)jc * KH + k) * Nn + i) * OUTF);
        __stcs(pp + lane, acc);
    }
}

// ============================================================
// K4: reduce partials over j-chunks, apply elu, write out.
// ============================================================
__global__ void __launch_bounds__(256) k4_reduce(float* __restrict__ out) {
    int idx = blockIdx.x * 256 + threadIdx.x;   // over Nn*KH*OUTF
    int i = idx >> 8, rem = idx & 255;
    int k = rem >> 6, f = rem & 63;
    float v = 0.f;
#pragma unroll
    for (int jc = 0; jc < JC; ++jc)
        v += __ldcs(&g_part[(((size_t)jc * KH + k) * Nn + i) * OUTF + f]);
    v = v > 0.f ? v : expm1f(v);
    out[idx] = v;
}

// ============================================================
extern "C" void kernel_launch(void* const* d_in, const int* in_sizes, int n_in,
                              void* d_out, int out_size) {
    const float *h = nullptr, *edge = nullptr, *W = nullptr, *a = nullptr;
    for (int q = 0; q < n_in; ++q) {
        switch (in_sizes[q]) {
            case Nn * INF_:    h = (const float*)d_in[q]; break;
            case INF_ * OUTF:  W = (const float*)d_in[q]; break;
            case 2 * OUTF:     a = (const float*)d_in[q]; break;
            default:
                if (in_sizes[q] == KH * Nn * Nn) edge = (const float*)d_in[q];
                break;
        }
    }
    if (!h || !edge || !W || !a) {
        if (n_in >= 4) {
            h    = (const float*)d_in[0];
            edge = (const float*)d_in[1];
            W    = (const float*)d_in[2];
            a    = (const float*)d_in[3];
        }
    }

    const long n_elu = (long)Nn * KH * OUTF;
    const long n_att = (long)KH * Nn * Nn;
    float* out = (float*)d_out;
    float* attp = out;
    int write_att = 0;
    if ((long)out_size >= n_elu + n_att) {
        attp = out + n_elu;
        write_att = 1;
    }

    const int smem = JW * (OUTF / 2) * (int)sizeof(__half2);   // 64KB
    cudaFuncSetAttribute(k3_chunk, cudaFuncAttributeMaxDynamicSharedMemorySize, smem);

    k1_wh   <<<Nn / 4,             256>>>(h, W, a);
    k2_stats<<<KH * 4 * SEG,       256>>>(edge);
    k2_merge<<<KH * Nn / 256,      256>>>();
    k3_chunk<<<KH * JC * IC,       1024, smem>>>(edge, attp, write_att);
    k4_reduce<<<Nn * KH * OUTF / 256, 256>>>(out);
}